// round 6
// baseline (speedup 1.0000x reference)
#include <cuda_runtime.h>
#include <cuda_bf16.h>
#include <cstdint>

#define BATCH 2
#define CH 64
#define HW 4096   // 64*64

typedef unsigned long long u64;

__device__ __forceinline__ u64 pk2(float lo, float hi) {
    u64 r; asm("mov.b64 %0,{%1,%2};" : "=l"(r) : "f"(lo), "f"(hi)); return r;
}
__device__ __forceinline__ void upk2(u64 v, float& lo, float& hi) {
    asm("mov.b64 {%0,%1},%2;" : "=f"(lo), "=f"(hi) : "l"(v));
}
__device__ __forceinline__ u64 ffma2(u64 a, u64 b, u64 c) {
    u64 d; asm("fma.rn.f32x2 %0,%1,%2,%3;" : "=l"(d) : "l"(a), "l"(b), "l"(c)); return d;
}

// ---------------- scratch ----------------
__device__ float g_scale[4 * CH];
__device__ float g_xg[BATCH * CH * HW];
__device__ float g_gg[BATCH * CH * HW];
__device__ float g_xq[BATCH * CH * HW];
__device__ float g_gq[BATCH * CH * HW];
__device__ float g_xout[BATCH * CH * HW];
__device__ float g_gout[BATCH * CH * HW];
__device__ float g_outb[BATCH * CH * HW];
__device__ float g_t1[BATCH * CH * HW];
__device__ float g_sc[BATCH * CH * HW];
// bf16 hi/lo K (per kind) and V, produced by kproj, consumed by kattn
__device__ __nv_bfloat16 g_bkh[2 * BATCH * CH * HW];
__device__ __nv_bfloat16 g_bkl[2 * BATCH * CH * HW];
__device__ __nv_bfloat16 g_bvh[BATCH * CH * HW];
__device__ __nv_bfloat16 g_bvl[BATCH * CH * HW];

#define BUF_XG 0
#define BUF_GG 1
#define BUF_OUT 2
#define BUF_T1 3

#define BUF_SC 5
#define BUF_OT1 6

__device__ __forceinline__ float* pick_in(int w) {
    switch (w) {
        case BUF_XG: return g_xg;
        case BUF_GG: return g_gg;
        case BUF_OUT: return g_outb;
        default:     return g_t1;
    }
}
__device__ __forceinline__ float* pick_out(int w) {
    switch (w) {
        case BUF_SC: return g_sc;
        default:     return g_t1;
    }
}

// ================= helpers =================
__device__ __forceinline__ uint32_t su32(const void* p) {
    uint32_t a;
    asm("{ .reg .u64 t; cvta.to.shared.u64 t, %1; cvt.u32.u64 %0, t; }" : "=r"(a) : "l"(p));
    return a;
}
__device__ __forceinline__ void mma_bf16(float* d, const uint32_t* a, uint32_t b0, uint32_t b1) {
    asm volatile(
        "mma.sync.aligned.m16n8k16.row.col.f32.bf16.bf16.f32 "
        "{%0,%1,%2,%3}, {%4,%5,%6,%7}, {%8,%9}, {%0,%1,%2,%3};"
        : "+f"(d[0]), "+f"(d[1]), "+f"(d[2]), "+f"(d[3])
        : "r"(a[0]), "r"(a[1]), "r"(a[2]), "r"(a[3]), "r"(b0), "r"(b1));
}
__device__ __forceinline__ void ldsm4(uint32_t* r, uint32_t addr) {
    asm volatile("ldmatrix.sync.aligned.m8n8.x4.shared.b16 {%0,%1,%2,%3}, [%4];"
                 : "=r"(r[0]), "=r"(r[1]), "=r"(r[2]), "=r"(r[3]) : "r"(addr));
}
__device__ __forceinline__ void ldsm4t(uint32_t* r, uint32_t addr) {
    asm volatile("ldmatrix.sync.aligned.m8n8.x4.trans.shared.b16 {%0,%1,%2,%3}, [%4];"
                 : "=r"(r[0]), "=r"(r[1]), "=r"(r[2]), "=r"(r[3]) : "r"(addr));
}
__device__ __forceinline__ uint32_t cvt_bf2(float lo, float hi) {
    uint32_t r;
    asm("cvt.rn.bf16x2.f32 %0, %1, %2;" : "=r"(r) : "f"(hi), "f"(lo));
    return r;
}
__device__ __forceinline__ void split2(float a, float b, uint32_t& hw, uint32_t& lw) {
    uint32_t h = cvt_bf2(a, b);
    float ra = a - __uint_as_float(h << 16);
    float rb = b - __uint_as_float(h & 0xFFFF0000u);
    hw = h;
    lw = cvt_bf2(ra, rb);
}
__device__ __forceinline__ void wrb(__nv_bfloat16* H, __nv_bfloat16* L, int idx, float v) {
    __nv_bfloat16 h = __float2bfloat16_rn(v);
    H[idx] = h;
    L[idx] = __float2bfloat16_rn(v - __bfloat162float(h));
}
__device__ __forceinline__ void cpa16(uint32_t dst, const void* src) {
    asm volatile("cp.async.cg.shared.global [%0], [%1], 16;" :: "r"(dst), "l"(src) : "memory");
}
#define CPA_COMMIT() asm volatile("cp.async.commit_group;" ::: "memory")
#define CPA_WAIT1()  asm volatile("cp.async.wait_group 1;" ::: "memory")
#define CPA_WAIT0()  asm volatile("cp.async.wait_group 0;" ::: "memory")

// ---------------- 1. channel attention scalars ----------------
__global__ void kstats(const float* __restrict__ x, const float* __restrict__ g,
                       const float* __restrict__ lw, const float* __restrict__ lb) {
    int idx = blockIdx.x;
    int t = idx >> 7, b = (idx >> 6) & 1, c = idx & 63;
    const float* in = (t ? g : x) + (b * CH + c) * HW;
    float s = 0.f;
    for (int i = threadIdx.x; i < HW; i += 256) s += in[i];
    __shared__ float red[8];
    #pragma unroll
    for (int o = 16; o > 0; o >>= 1) s += __shfl_xor_sync(0xffffffffu, s, o);
    if ((threadIdx.x & 31) == 0) red[threadIdx.x >> 5] = s;
    __syncthreads();
    if (threadIdx.x == 0) {
        float tot = 0.f;
        #pragma unroll
        for (int i = 0; i < 8; i++) tot += red[i];
        float p = tot * (1.0f / (float)HW);
        float W = lw[0], B = lb[0];
        float h = p * W + B;
        h = h > 0.f ? h : 0.1f * h;
        float z = h * W + B;
        g_scale[idx] = 1.f / (1.f + expf(-z));
    }
}

// ---------------- 2. gated coord conv: 8 oc per block ----------------
__global__ void __launch_bounds__(256) kgated(const float* __restrict__ xin,
                                              const float* __restrict__ gin,
                                              const float* __restrict__ cw) {
    int z = blockIdx.z;
    int t = z >> 1, b = z & 1;
    const float* in = (t ? gin : xin) + b * CH * HW;
    float* out = (t ? g_gg : g_xg) + b * CH * HW;
    int ocg = blockIdx.y;   // 8 groups of 8 oc

    __shared__ float ws[8 * 66 * 9];
    for (int i = threadIdx.x; i < 8 * 594; i += 256) {
        int o = i / 594, r = i % 594;
        ws[o * 594 + r] = cw[(ocg * 8 + o) * 594 + r];
    }
    __syncthreads();

    int p = blockIdx.x * 1024 + threadIdx.x * 4;
    int row = p >> 6, col0 = p & 63;
    float acc[8][4];
    #pragma unroll
    for (int o = 0; o < 8; o++)
        #pragma unroll
        for (int u = 0; u < 4; u++) acc[o][u] = 0.f;

    for (int ic = 0; ic < 64; ic++) {
        const float* ch = in + ic * HW;
        #pragma unroll
        for (int kh = 0; kh < 3; kh++) {
            int hh = row + kh - 1;
            if ((unsigned)hh >= 64u) continue;
            float v[6];
            #pragma unroll
            for (int u = 0; u < 6; u++) {
                int cc = col0 - 1 + u;
                v[u] = ((unsigned)cc < 64u) ? ch[hh * 64 + cc] : 0.f;
            }
            #pragma unroll
            for (int o = 0; o < 8; o++) {
                const float* wr = &ws[o * 594 + ic * 9 + kh * 3];
                #pragma unroll
                for (int kw = 0; kw < 3; kw++) {
                    float wv = wr[kw];
                    acc[o][0] += wv * v[kw + 0];
                    acc[o][1] += wv * v[kw + 1];
                    acc[o][2] += wv * v[kw + 2];
                    acc[o][3] += wv * v[kw + 3];
                }
            }
        }
    }
    #pragma unroll
    for (int ic = 64; ic < 66; ic++) {
        #pragma unroll
        for (int kh = 0; kh < 3; kh++) {
            int hh = row + kh - 1;
            if ((unsigned)hh >= 64u) continue;
            float yyv = (float)hh * (2.f / 63.f) - 1.f;
            float v[6];
            #pragma unroll
            for (int u = 0; u < 6; u++) {
                int cc = col0 - 1 + u;
                float val = 0.f;
                if ((unsigned)cc < 64u)
                    val = (ic == 64) ? ((float)cc * (2.f / 63.f) - 1.f) : yyv;
                v[u] = val;
            }
            #pragma unroll
            for (int o = 0; o < 8; o++) {
                const float* wr = &ws[o * 594 + ic * 9 + kh * 3];
                #pragma unroll
                for (int kw = 0; kw < 3; kw++) {
                    float wv = wr[kw];
                    acc[o][0] += wv * v[kw + 0];
                    acc[o][1] += wv * v[kw + 1];
                    acc[o][2] += wv * v[kw + 2];
                    acc[o][3] += wv * v[kw + 3];
                }
            }
        }
    }

    #pragma unroll
    for (int o = 0; o < 8; o++) {
        int oc = ocg * 8 + o;
        float s = g_scale[z * CH + oc];
        float* op = out + oc * HW + p;
        *(float4*)op = make_float4(s * acc[o][0], s * acc[o][1], s * acc[o][2], s * acc[o][3]);
    }
}

// ---------------- 3. fused QKV projections; K/V written as bf16 hi/lo ----------------
__global__ void __launch_bounds__(128) kproj(
    const float* __restrict__ xq_w, const float* __restrict__ xq_b,
    const float* __restrict__ xk_w, const float* __restrict__ xk_b,
    const float* __restrict__ xv_w, const float* __restrict__ xv_b,
    const float* __restrict__ gq_w, const float* __restrict__ gq_b,
    const float* __restrict__ gk_w, const float* __restrict__ gk_b) {
    __shared__ float si[64 * 128];
    __shared__ float swt[3 * 512];
    __shared__ float sb2[3 * 8];

    int z = blockIdx.z;
    int side = z >> 1, b = z & 1;
    int og = blockIdx.y;
    int n0 = blockIdx.x * 128;
    int tid = threadIdx.x;

    const float* in = (side ? g_gg : g_xg) + b * CH * HW;
    const float* ws[3];
    const float* bs[3];
    int nset;
    if (side == 0) {
        ws[0] = xq_w; ws[1] = xk_w; ws[2] = xv_w;
        bs[0] = xq_b; bs[1] = xk_b; bs[2] = xv_b;
        nset = 3;
    } else {
        ws[0] = gq_w; ws[1] = gk_w; ws[2] = gk_w;
        bs[0] = gq_b; bs[1] = gk_b; bs[2] = gk_b;
        nset = 2;
    }

    for (int i = tid; i < 2048; i += 128) {
        int c = i >> 5, p4 = (i & 31) * 4;
        *(float4*)(si + c * 128 + p4) = *(const float4*)(in + c * HW + n0 + p4);
    }
    for (int s = 0; s < nset; s++) {
        for (int i = tid; i < 512; i += 128) {
            int c = i >> 3, o = i & 7;
            swt[s * 512 + c * 8 + o] = ws[s][(og * 8 + o) * 64 + c];
        }
        if (tid < 8) sb2[s * 8 + tid] = bs[s][og * 8 + tid];
    }
    __syncthreads();

    u64 acc[3][4];
    #pragma unroll
    for (int s = 0; s < 3; s++)
        #pragma unroll
        for (int k = 0; k < 4; k++)
            acc[s][k] = pk2(sb2[s * 8 + 2 * k], sb2[s * 8 + 2 * k + 1]);

    if (side == 0) {
        for (int c = 0; c < 64; c++) {
            float iv = si[c * 128 + tid];
            u64 ivp = pk2(iv, iv);
            #pragma unroll
            for (int s = 0; s < 3; s++) {
                ulonglong2 wa = *(const ulonglong2*)(swt + s * 512 + c * 8);
                ulonglong2 wb = *(const ulonglong2*)(swt + s * 512 + c * 8 + 4);
                acc[s][0] = ffma2(ivp, wa.x, acc[s][0]);
                acc[s][1] = ffma2(ivp, wa.y, acc[s][1]);
                acc[s][2] = ffma2(ivp, wb.x, acc[s][2]);
                acc[s][3] = ffma2(ivp, wb.y, acc[s][3]);
            }
        }
    } else {
        for (int c = 0; c < 64; c++) {
            float iv = si[c * 128 + tid];
            u64 ivp = pk2(iv, iv);
            #pragma unroll
            for (int s = 0; s < 2; s++) {
                ulonglong2 wa = *(const ulonglong2*)(swt + s * 512 + c * 8);
                ulonglong2 wb = *(const ulonglong2*)(swt + s * 512 + c * 8 + 4);
                acc[s][0] = ffma2(ivp, wa.x, acc[s][0]);
                acc[s][1] = ffma2(ivp, wa.y, acc[s][1]);
                acc[s][2] = ffma2(ivp, wb.x, acc[s][2]);
                acc[s][3] = ffma2(ivp, wb.y, acc[s][3]);
            }
        }
    }

    // epilogue: q -> fp32; k -> bf16 hi/lo (per kind=side); v (side 0) -> bf16 hi/lo
    float* qdst = side ? g_gq : g_xq;
    __nv_bfloat16* KhD = g_bkh + (long)side * BATCH * CH * HW;
    __nv_bfloat16* KlD = g_bkl + (long)side * BATCH * CH * HW;
    #pragma unroll
    for (int k = 0; k < 4; k++) {
        int i0 = (b * CH + og * 8 + 2 * k) * HW + n0 + tid;
        float lo, hi;
        upk2(acc[0][k], lo, hi);
        qdst[i0] = lo; qdst[i0 + HW] = hi;
        upk2(acc[1][k], lo, hi);
        wrb(KhD, KlD, i0, lo); wrb(KhD, KlD, i0 + HW, hi);
        if (side == 0) {
            upk2(acc[2][k], lo, hi);
            wrb(g_bvh, g_bvl, i0, lo); wrb(g_bvh, g_bvl, i0 + HW, hi);
        }
    }
}

// ---------------- 4. flash attention: mma.sync + cp.async double buffer ----------------
// grid (64, B, 2), block 128 = 4 warps. CTA: 64 Q-rows; warp: 16 rows.
// dyn smem: 2 buffers x {Kh,Kl,Vh,Vl} each 64x72 bf16 (9216 B) = 73728 B.
__global__ void __launch_bounds__(128) kattn() {
    extern __shared__ __align__(16) uint8_t dyn[];

    const int tid = threadIdx.x;
    const int lane = tid & 31, wid = tid >> 5;
    const int tg = lane & 3, g = lane >> 2;
    const int b = blockIdx.y, kind = blockIdx.z;
    const int n0 = blockIdx.x * 64;
    const float* Qp = (kind ? g_gq : g_xq) + b * CH * HW;
    const __nv_bfloat16* Kh = g_bkh + ((long)kind * BATCH + b) * CH * HW;
    const __nv_bfloat16* Kl = g_bkl + ((long)kind * BATCH + b) * CH * HW;
    const __nv_bfloat16* Vh = g_bvh + (long)b * CH * HW;
    const __nv_bfloat16* Vl = g_bvl + (long)b * CH * HW;
    float* Op = (kind ? g_gout : g_xout) + b * CH * HW;

    const uint32_t sb = su32(dyn);

    // ---- stage Q (hi/lo) into buf0 area, load A-frags, then release buffer ----
    {
        __nv_bfloat16* Qh = (__nv_bfloat16*)dyn;           // [64][72]
        __nv_bfloat16* Ql = (__nv_bfloat16*)(dyn + 9216);
        for (int idx = tid; idx < 4096; idx += 128) {
            int i = idx & 63, c = idx >> 6;
            float a = Qp[c * HW + n0 + i];
            __nv_bfloat16 h = __float2bfloat16_rn(a);
            Qh[i * 72 + c] = h;
            Ql[i * 72 + c] = __float2bfloat16_rn(a - __bfloat162float(h));
        }
    }
    __syncthreads();

    uint32_t qh[4][4], ql[4][4];
    {
        int rl = lane & 15, ca = (lane >> 4) << 3;
        #pragma unroll
        for (int kc = 0; kc < 4; kc++) {
            uint32_t off = (uint32_t)(((16 * wid + rl) * 72 + 16 * kc + ca) * 2);
            ldsm4(qh[kc], sb + off);
            ldsm4(ql[kc], sb + 9216 + off);
        }
    }
    __syncthreads();

    float oacc[8][4];
    #pragma unroll
    for (int cb = 0; cb < 8; cb++) {
        oacc[cb][0] = 0.f; oacc[cb][1] = 0.f; oacc[cb][2] = 0.f; oacc[cb][3] = 0.f;
    }
    float mrow0 = -1e30f, mrow1 = -1e30f, lrow0 = 0.f, lrow1 = 0.f;

    const uint32_t k_off = (uint32_t)(((lane & 15) * 72 + ((lane >> 4) << 3)) * 2);
    const uint32_t v_off = (uint32_t)(((((lane >> 4) << 3) + (lane & 7)) * 72 +
                                      (((lane >> 3) & 1) << 3)) * 2);

    // prefetch tile 0 into buf0
    {
        #pragma unroll
        for (int u = 0; u < 4; u++) {
            int i = tid + u * 128;
            int row = i >> 3, ch = i & 7;
            uint32_t dst = sb + row * 144 + ch * 16;
            long go = (long)row * HW + ch * 8;
            cpa16(dst,          Kh + go);
            cpa16(dst + 9216,   Kl + go);
            cpa16(dst + 18432,  Vh + go);
            cpa16(dst + 27648,  Vl + go);
        }
        CPA_COMMIT();
    }

    for (int kt = 0; kt < 64; kt++) {
        const uint32_t bufc = sb + (uint32_t)(kt & 1) * 36864;

        if (kt < 63) {
            uint32_t bufn = sb + (uint32_t)((kt + 1) & 1) * 36864;
            int m0n = (kt + 1) * 64;
            #pragma unroll
            for (int u = 0; u < 4; u++) {
                int i = tid + u * 128;
                int row = i >> 3, ch = i & 7;
                uint32_t dst = bufn + row * 144 + ch * 16;
                long go = (long)row * HW + m0n + ch * 8;
                cpa16(dst,          Kh + go);
                cpa16(dst + 9216,   Kl + go);
                cpa16(dst + 18432,  Vh + go);
                cpa16(dst + 27648,  Vl + go);
            }
            CPA_COMMIT();
            CPA_WAIT1();
        } else {
            CPA_WAIT0();
        }
        __syncthreads();

        // ---- S = Q K^T (3 bf16 passes) ----
        float sa[8][4];
        #pragma unroll
        for (int nb = 0; nb < 8; nb++) {
            sa[nb][0] = 0.f; sa[nb][1] = 0.f; sa[nb][2] = 0.f; sa[nb][3] = 0.f;
        }
        #pragma unroll
        for (int kc = 0; kc < 4; kc++) {
            #pragma unroll
            for (int jb = 0; jb < 4; jb++) {
                uint32_t bh[4], bl[4];
                uint32_t toff = (uint32_t)((kc * 16 * 72 + jb * 16) * 2);
                ldsm4t(bh, bufc + k_off + toff);
                ldsm4t(bl, bufc + 9216 + k_off + toff);
                mma_bf16(sa[2 * jb],     qh[kc], bh[0], bh[1]);
                mma_bf16(sa[2 * jb],     qh[kc], bl[0], bl[1]);
                mma_bf16(sa[2 * jb],     ql[kc], bh[0], bh[1]);
                mma_bf16(sa[2 * jb + 1], qh[kc], bh[2], bh[3]);
                mma_bf16(sa[2 * jb + 1], qh[kc], bl[2], bl[3]);
                mma_bf16(sa[2 * jb + 1], ql[kc], bh[2], bh[3]);
            }
        }

        // ---- online softmax ----
        float tm0 = -1e30f, tm1 = -1e30f;
        #pragma unroll
        for (int nb = 0; nb < 8; nb++) {
            tm0 = fmaxf(tm0, fmaxf(sa[nb][0], sa[nb][1]));
            tm1 = fmaxf(tm1, fmaxf(sa[nb][2], sa[nb][3]));
        }
        tm0 = fmaxf(tm0, __shfl_xor_sync(0xffffffffu, tm0, 1));
        tm0 = fmaxf(tm0, __shfl_xor_sync(0xffffffffu, tm0, 2));
        tm1 = fmaxf(tm1, __shfl_xor_sync(0xffffffffu, tm1, 1));
        tm1 = fmaxf(tm1, __shfl_xor_sync(0xffffffffu, tm1, 2));
        float mn0 = fmaxf(mrow0, tm0), mn1 = fmaxf(mrow1, tm1);
        float corr0 = __expf(mrow0 - mn0), corr1 = __expf(mrow1 - mn1);
        mrow0 = mn0; mrow1 = mn1;

        float ps0 = 0.f, ps1 = 0.f;
        #pragma unroll
        for (int nb = 0; nb < 8; nb++) {
            sa[nb][0] = __expf(sa[nb][0] - mn0);
            sa[nb][1] = __expf(sa[nb][1] - mn0);
            sa[nb][2] = __expf(sa[nb][2] - mn1);
            sa[nb][3] = __expf(sa[nb][3] - mn1);
            ps0 += sa[nb][0] + sa[nb][1];
            ps1 += sa[nb][2] + sa[nb][3];
        }
        ps0 += __shfl_xor_sync(0xffffffffu, ps0, 1);
        ps0 += __shfl_xor_sync(0xffffffffu, ps0, 2);
        ps1 += __shfl_xor_sync(0xffffffffu, ps1, 1);
        ps1 += __shfl_xor_sync(0xffffffffu, ps1, 2);
        lrow0 = lrow0 * corr0 + ps0;
        lrow1 = lrow1 * corr1 + ps1;

        #pragma unroll
        for (int cb = 0; cb < 8; cb++) {
            oacc[cb][0] *= corr0; oacc[cb][1] *= corr0;
            oacc[cb][2] *= corr1; oacc[cb][3] *= corr1;
        }

        // ---- P a-frags in registers (hi/lo) ----
        uint32_t ph[4][4], pl[4][4];
        #pragma unroll
        for (int kc = 0; kc < 4; kc++) {
            split2(sa[2 * kc][0],     sa[2 * kc][1],     ph[kc][0], pl[kc][0]);
            split2(sa[2 * kc][2],     sa[2 * kc][3],     ph[kc][1], pl[kc][1]);
            split2(sa[2 * kc + 1][0], sa[2 * kc + 1][1], ph[kc][2], pl[kc][2]);
            split2(sa[2 * kc + 1][2], sa[2 * kc + 1][3], ph[kc][3], pl[kc][3]);
        }

        // ---- O += P V^T (3 bf16 passes) ----
        #pragma unroll
        for (int kc = 0; kc < 4; kc++) {
            #pragma unroll
            for (int cp = 0; cp < 4; cp++) {
                uint32_t bh[4], bl[4];
                uint32_t toff = (uint32_t)((cp * 16 * 72 + kc * 16) * 2);
                ldsm4(bh, bufc + 18432 + v_off + toff);
                ldsm4(bl, bufc + 27648 + v_off + toff);
                mma_bf16(oacc[2 * cp],     ph[kc], bh[0], bh[1]);
                mma_bf16(oacc[2 * cp],     ph[kc], bl[0], bl[1]);
                mma_bf16(oacc[2 * cp],     pl[kc], bh[0], bh[1]);
                mma_bf16(oacc[2 * cp + 1], ph[kc], bh[2], bh[3]);
                mma_bf16(oacc[2 * cp + 1], ph[kc], bl[2], bl[3]);
                mma_bf16(oacc[2 * cp + 1], pl[kc], bh[2], bh[3]);
            }
        }
        __syncthreads();
    }

    // ---- epilogue ----
    float inv0 = 1.f / lrow0, inv1 = 1.f / lrow1;
    int i0 = n0 + 16 * wid + g;
    #pragma unroll
    for (int cb = 0; cb < 8; cb++) {
        int c = 8 * cb + 2 * tg;
        Op[c * HW + i0]           = oacc[cb][0] * inv0;
        Op[(c + 1) * HW + i0]     = oacc[cb][1] * inv0;
        Op[c * HW + i0 + 8]       = oacc[cb][2] * inv1;
        Op[(c + 1) * HW + i0 + 8] = oacc[cb][3] * inv1;
    }
}

// ---------------- 5. combine ----------------
__global__ void kcombine(const float* __restrict__ gamma, const float* __restrict__ alpha) {
    int i = blockIdx.x * 256 + threadIdx.x;
    g_outb[i] = gamma[0] * g_xout[i] + alpha[0] * g_gout[i];
}

// ---------------- 6. plain conv3x3: 8 oc per block, optional fused final ----------------
__global__ void __launch_bounds__(256) kconv3(const float* __restrict__ w,
                                              const float* __restrict__ bias,
                                              int in_id, int out_id, int leaky_in,
                                              int finalize, float* __restrict__ dout) {
    const float* inb = pick_in(in_id);
    int b = blockIdx.z, ocg = blockIdx.y;

    __shared__ float ws[8 * 576];
    for (int i = threadIdx.x; i < 8 * 576; i += 256) {
        int o = i / 576, r = i % 576;
        ws[o * 576 + r] = w[(ocg * 8 + o) * 576 + r];
    }
    __syncthreads();

    int p = blockIdx.x * 1024 + threadIdx.x * 4;
    int row = p >> 6, col0 = p & 63;
    float acc[8][4];
    #pragma unroll
    for (int o = 0; o < 8; o++) {
        float bv = bias[ocg * 8 + o];
        #pragma unroll
        for (int u = 0; u < 4; u++) acc[o][u] = bv;
    }
    const float* in = inb + b * CH * HW;

    for (int ic = 0; ic < 64; ic++) {
        const float* ch = in + ic * HW;
        #pragma unroll
        for (int kh = 0; kh < 3; kh++) {
            int hh = row + kh - 1;
            if ((unsigned)hh >= 64u) continue;
            float v[6];
            #pragma unroll
            for (int u = 0; u < 6; u++) {
                int cc = col0 - 1 + u;
                float val = ((unsigned)cc < 64u) ? ch[hh * 64 + cc] : 0.f;
                if (leaky_in) val = val > 0.f ? val : 0.1f * val;
                v[u] = val;
            }
            #pragma unroll
            for (int o = 0; o < 8; o++) {
                const float* wr = &ws[o * 576 + ic * 9 + kh * 3];
                #pragma unroll
                for (int kw = 0; kw < 3; kw++) {
                    float wv = wr[kw];
                    acc[o][0] += wv * v[kw + 0];
                    acc[o][1] += wv * v[kw + 1];
                    acc[o][2] += wv * v[kw + 2];
                    acc[o][3] += wv * v[kw + 3];
                }
            }
        }
    }
    if (finalize) {
        #pragma unroll
        for (int o = 0; o < 8; o++) {
            int base = (b * CH + ocg * 8 + o) * HW + p;
            float4 scv = *(const float4*)(g_sc + base);
            float4 gov = *(const float4*)(g_gout + base);
            *(float4*)(dout + base) = make_float4(acc[o][0] + scv.x * gov.x,
                                                  acc[o][1] + scv.y * gov.y,
                                                  acc[o][2] + scv.z * gov.z,
                                                  acc[o][3] + scv.w * gov.w);
        }
    } else {
        float* outb = pick_out(out_id);
        #pragma unroll
        for (int o = 0; o < 8; o++) {
            float* op = outb + (b * CH + ocg * 8 + o) * HW + p;
            *(float4*)op = make_float4(acc[o][0], acc[o][1], acc[o][2], acc[o][3]);
        }
    }
}

// ---------------- 3b. 1x1 conv (shortcut path) ----------------
__global__ void k1x1(const float* __restrict__ w, const float* __restrict__ bias,
                     int in_id, int out_id) {
    const float* in = pick_in(in_id);
    float* out = pick_out(out_id);
    int b = blockIdx.z, og = blockIdx.y;
    int n0 = blockIdx.x * 128;

    __shared__ float si[64 * 128];
    __shared__ float sw[8 * 64];
    for (int i = threadIdx.x; i < 64 * 128; i += 128) {
        int c = i >> 7, px = i & 127;
        si[i] = in[(b * CH + c) * HW + n0 + px];
    }
    for (int i = threadIdx.x; i < 512; i += 128)
        sw[i] = w[(og * 8 + (i >> 6)) * 64 + (i & 63)];
    __syncthreads();

    float acc[8];
    #pragma unroll
    for (int o = 0; o < 8; o++) acc[o] = bias[og * 8 + o];
    for (int c = 0; c < 64; c++) {
        float iv = si[c * 128 + threadIdx.x];
        #pragma unroll
        for (int o = 0; o < 8; o++) acc[o] += sw[o * 64 + c] * iv;
    }
    #pragma unroll
    for (int o = 0; o < 8; o++)
        out[(b * CH + og * 8 + o) * HW + n0 + threadIdx.x] = acc[o];
}

extern "C" void kernel_launch(void* const* d_in, const int* in_sizes, int n_in,
                              void* d_out, int out_size) {
    const float* x       = (const float*)d_in[0];
    const float* guide   = (const float*)d_in[1];
    const float* lin_w   = (const float*)d_in[2];
    const float* lin_b   = (const float*)d_in[3];
    const float* coord_w = (const float*)d_in[4];
    const float* xq_w = (const float*)d_in[5];
    const float* xq_b = (const float*)d_in[6];
    const float* xk_w = (const float*)d_in[7];
    const float* xk_b = (const float*)d_in[8];
    const float* xv_w = (const float*)d_in[9];
    const float* xv_b = (const float*)d_in[10];
    const float* gq_w = (const float*)d_in[11];
    const float* gq_b = (const float*)d_in[12];
    const float* gk_w = (const float*)d_in[13];
    const float* gk_b = (const float*)d_in[14];
    const float* gamma = (const float*)d_in[15];
    const float* alpha = (const float*)d_in[16];
    const float* c1_w = (const float*)d_in[17];
    const float* c1_b = (const float*)d_in[18];
    const float* c2_w = (const float*)d_in[19];
    const float* c2_b = (const float*)d_in[20];
    const float* sc_w = (const float*)d_in[21];
    const float* sc_b = (const float*)d_in[22];
    float* out = (float*)d_out;

    cudaFuncSetAttribute(kattn, cudaFuncAttributeMaxDynamicSharedMemorySize, 73728);

    kstats<<<256, 256>>>(x, guide, lin_w, lin_b);
    kgated<<<dim3(4, 8, 4), 256>>>(x, guide, coord_w);

    kproj<<<dim3(32, 8, 4), 128>>>(xq_w, xq_b, xk_w, xk_b, xv_w, xv_b,
                                   gq_w, gq_b, gk_w, gk_b);

    kattn<<<dim3(64, BATCH, 2), 128, 73728>>>();

    kcombine<<<2048, 256>>>(gamma, alpha);

    kconv3<<<dim3(4, 8, BATCH), 256>>>(c1_w, c1_b, BUF_OUT, BUF_OT1, 1, 0, nullptr);
    k1x1<<<dim3(32, 8, BATCH), 128>>>(sc_w, sc_b, BUF_OUT, BUF_SC);
    kconv3<<<dim3(4, 8, BATCH), 256>>>(c2_w, c2_b, BUF_T1, 0, 1, 1, out);
}

// round 7
// speedup vs baseline: 1.1202x; 1.1202x over previous
#include <cuda_runtime.h>
#include <cuda_bf16.h>
#include <cstdint>

#define BATCH 2
#define CH 64
#define HW 4096   // 64*64

typedef unsigned long long u64;

__device__ __forceinline__ u64 pk2(float lo, float hi) {
    u64 r; asm("mov.b64 %0,{%1,%2};" : "=l"(r) : "f"(lo), "f"(hi)); return r;
}
__device__ __forceinline__ void upk2(u64 v, float& lo, float& hi) {
    asm("mov.b64 {%0,%1},%2;" : "=f"(lo), "=f"(hi) : "l"(v));
}
__device__ __forceinline__ u64 ffma2(u64 a, u64 b, u64 c) {
    u64 d; asm("fma.rn.f32x2 %0,%1,%2,%3;" : "=l"(d) : "l"(a), "l"(b), "l"(c)); return d;
}

// ---------------- scratch ----------------
__device__ float g_scale[4 * CH];
__device__ float g_xg[BATCH * CH * HW];
__device__ float g_gg[BATCH * CH * HW];
__device__ float g_xq[BATCH * CH * HW];
__device__ float g_gq[BATCH * CH * HW];
__device__ float g_xout[BATCH * CH * HW];
__device__ float g_gout[BATCH * CH * HW];
__device__ float g_outb[BATCH * CH * HW];
__device__ float g_t1[BATCH * CH * HW];
__device__ float g_sc[BATCH * CH * HW];
// bf16 hi/lo K (per kind) and V, produced by kproj, consumed by kattn
__device__ __nv_bfloat16 g_bkh[2 * BATCH * CH * HW];
__device__ __nv_bfloat16 g_bkl[2 * BATCH * CH * HW];
__device__ __nv_bfloat16 g_bvh[BATCH * CH * HW];
__device__ __nv_bfloat16 g_bvl[BATCH * CH * HW];

#define BUF_XG 0
#define BUF_GG 1
#define BUF_OUT 2
#define BUF_T1 3

#define BUF_SC 5
#define BUF_OT1 6

__device__ __forceinline__ float* pick_in(int w) {
    switch (w) {
        case BUF_XG: return g_xg;
        case BUF_GG: return g_gg;
        case BUF_OUT: return g_outb;
        default:     return g_t1;
    }
}
__device__ __forceinline__ float* pick_out(int w) {
    switch (w) {
        case BUF_SC: return g_sc;
        default:     return g_t1;
    }
}

// ================= helpers =================
__device__ __forceinline__ uint32_t su32(const void* p) {
    uint32_t a;
    asm("{ .reg .u64 t; cvta.to.shared.u64 t, %1; cvt.u32.u64 %0, t; }" : "=r"(a) : "l"(p));
    return a;
}
__device__ __forceinline__ void mma_bf16(float* d, const uint32_t* a, uint32_t b0, uint32_t b1) {
    asm volatile(
        "mma.sync.aligned.m16n8k16.row.col.f32.bf16.bf16.f32 "
        "{%0,%1,%2,%3}, {%4,%5,%6,%7}, {%8,%9}, {%0,%1,%2,%3};"
        : "+f"(d[0]), "+f"(d[1]), "+f"(d[2]), "+f"(d[3])
        : "r"(a[0]), "r"(a[1]), "r"(a[2]), "r"(a[3]), "r"(b0), "r"(b1));
}
__device__ __forceinline__ void ldsm4(uint32_t* r, uint32_t addr) {
    asm volatile("ldmatrix.sync.aligned.m8n8.x4.shared.b16 {%0,%1,%2,%3}, [%4];"
                 : "=r"(r[0]), "=r"(r[1]), "=r"(r[2]), "=r"(r[3]) : "r"(addr));
}
__device__ __forceinline__ void ldsm4t(uint32_t* r, uint32_t addr) {
    asm volatile("ldmatrix.sync.aligned.m8n8.x4.trans.shared.b16 {%0,%1,%2,%3}, [%4];"
                 : "=r"(r[0]), "=r"(r[1]), "=r"(r[2]), "=r"(r[3]) : "r"(addr));
}
__device__ __forceinline__ uint32_t cvt_bf2(float lo, float hi) {
    uint32_t r;
    asm("cvt.rn.bf16x2.f32 %0, %1, %2;" : "=r"(r) : "f"(hi), "f"(lo));
    return r;
}
__device__ __forceinline__ void split2(float a, float b, uint32_t& hw, uint32_t& lw) {
    uint32_t h = cvt_bf2(a, b);
    float ra = a - __uint_as_float(h << 16);
    float rb = b - __uint_as_float(h & 0xFFFF0000u);
    hw = h;
    lw = cvt_bf2(ra, rb);
}
__device__ __forceinline__ void wrb(__nv_bfloat16* H, __nv_bfloat16* L, int idx, float v) {
    __nv_bfloat16 h = __float2bfloat16_rn(v);
    H[idx] = h;
    L[idx] = __float2bfloat16_rn(v - __bfloat162float(h));
}
__device__ __forceinline__ void cpa16(uint32_t dst, const void* src) {
    asm volatile("cp.async.cg.shared.global [%0], [%1], 16;" :: "r"(dst), "l"(src) : "memory");
}
#define CPA_COMMIT() asm volatile("cp.async.commit_group;" ::: "memory")
#define CPA_WAIT1()  asm volatile("cp.async.wait_group 1;" ::: "memory")
#define CPA_WAIT0()  asm volatile("cp.async.wait_group 0;" ::: "memory")

// ---------------- 1. channel attention scalars ----------------
__global__ void kstats(const float* __restrict__ x, const float* __restrict__ g,
                       const float* __restrict__ lw, const float* __restrict__ lb) {
    int idx = blockIdx.x;
    int t = idx >> 7, b = (idx >> 6) & 1, c = idx & 63;
    const float* in = (t ? g : x) + (b * CH + c) * HW;
    float s = 0.f;
    for (int i = threadIdx.x; i < HW; i += 256) s += in[i];
    __shared__ float red[8];
    #pragma unroll
    for (int o = 16; o > 0; o >>= 1) s += __shfl_xor_sync(0xffffffffu, s, o);
    if ((threadIdx.x & 31) == 0) red[threadIdx.x >> 5] = s;
    __syncthreads();
    if (threadIdx.x == 0) {
        float tot = 0.f;
        #pragma unroll
        for (int i = 0; i < 8; i++) tot += red[i];
        float p = tot * (1.0f / (float)HW);
        float W = lw[0], B = lb[0];
        float h = p * W + B;
        h = h > 0.f ? h : 0.1f * h;
        float z = h * W + B;
        g_scale[idx] = 1.f / (1.f + expf(-z));
    }
}

// ---------------- 2. gated coord conv: 4 oc per block ----------------
__global__ void __launch_bounds__(256) kgated(const float* __restrict__ xin,
                                              const float* __restrict__ gin,
                                              const float* __restrict__ cw) {
    int z = blockIdx.z;
    int t = z >> 1, b = z & 1;
    const float* in = (t ? gin : xin) + b * CH * HW;
    float* out = (t ? g_gg : g_xg) + b * CH * HW;
    int ocg = blockIdx.y;   // 16 groups of 4 oc

    __shared__ float ws[4 * 66 * 9];
    for (int i = threadIdx.x; i < 4 * 594; i += 256) {
        int o = i / 594, r = i % 594;
        ws[o * 594 + r] = cw[(ocg * 4 + o) * 594 + r];
    }
    __syncthreads();

    int p = blockIdx.x * 1024 + threadIdx.x * 4;
    int row = p >> 6, col0 = p & 63;
    float acc[4][4];
    #pragma unroll
    for (int o = 0; o < 4; o++)
        #pragma unroll
        for (int u = 0; u < 4; u++) acc[o][u] = 0.f;

    for (int ic = 0; ic < 64; ic++) {
        const float* ch = in + ic * HW;
        #pragma unroll
        for (int kh = 0; kh < 3; kh++) {
            int hh = row + kh - 1;
            if ((unsigned)hh >= 64u) continue;
            float v[6];
            #pragma unroll
            for (int u = 0; u < 6; u++) {
                int cc = col0 - 1 + u;
                v[u] = ((unsigned)cc < 64u) ? ch[hh * 64 + cc] : 0.f;
            }
            #pragma unroll
            for (int o = 0; o < 4; o++) {
                const float* wr = &ws[o * 594 + ic * 9 + kh * 3];
                #pragma unroll
                for (int kw = 0; kw < 3; kw++) {
                    float wv = wr[kw];
                    acc[o][0] += wv * v[kw + 0];
                    acc[o][1] += wv * v[kw + 1];
                    acc[o][2] += wv * v[kw + 2];
                    acc[o][3] += wv * v[kw + 3];
                }
            }
        }
    }
    #pragma unroll
    for (int ic = 64; ic < 66; ic++) {
        #pragma unroll
        for (int kh = 0; kh < 3; kh++) {
            int hh = row + kh - 1;
            if ((unsigned)hh >= 64u) continue;
            float yyv = (float)hh * (2.f / 63.f) - 1.f;
            float v[6];
            #pragma unroll
            for (int u = 0; u < 6; u++) {
                int cc = col0 - 1 + u;
                float val = 0.f;
                if ((unsigned)cc < 64u)
                    val = (ic == 64) ? ((float)cc * (2.f / 63.f) - 1.f) : yyv;
                v[u] = val;
            }
            #pragma unroll
            for (int o = 0; o < 4; o++) {
                const float* wr = &ws[o * 594 + ic * 9 + kh * 3];
                #pragma unroll
                for (int kw = 0; kw < 3; kw++) {
                    float wv = wr[kw];
                    acc[o][0] += wv * v[kw + 0];
                    acc[o][1] += wv * v[kw + 1];
                    acc[o][2] += wv * v[kw + 2];
                    acc[o][3] += wv * v[kw + 3];
                }
            }
        }
    }

    #pragma unroll
    for (int o = 0; o < 4; o++) {
        int oc = ocg * 4 + o;
        float s = g_scale[z * CH + oc];
        float* op = out + oc * HW + p;
        *(float4*)op = make_float4(s * acc[o][0], s * acc[o][1], s * acc[o][2], s * acc[o][3]);
    }
}

// ---------------- 3. fused QKV projections; K/V written as bf16 hi/lo ----------------
__global__ void __launch_bounds__(128) kproj(
    const float* __restrict__ xq_w, const float* __restrict__ xq_b,
    const float* __restrict__ xk_w, const float* __restrict__ xk_b,
    const float* __restrict__ xv_w, const float* __restrict__ xv_b,
    const float* __restrict__ gq_w, const float* __restrict__ gq_b,
    const float* __restrict__ gk_w, const float* __restrict__ gk_b) {
    __shared__ float si[64 * 128];
    __shared__ float swt[3 * 512];
    __shared__ float sb2[3 * 8];

    int z = blockIdx.z;
    int side = z >> 1, b = z & 1;
    int og = blockIdx.y;
    int n0 = blockIdx.x * 128;
    int tid = threadIdx.x;

    const float* in = (side ? g_gg : g_xg) + b * CH * HW;
    const float* ws[3];
    const float* bs[3];
    int nset;
    if (side == 0) {
        ws[0] = xq_w; ws[1] = xk_w; ws[2] = xv_w;
        bs[0] = xq_b; bs[1] = xk_b; bs[2] = xv_b;
        nset = 3;
    } else {
        ws[0] = gq_w; ws[1] = gk_w; ws[2] = gk_w;
        bs[0] = gq_b; bs[1] = gk_b; bs[2] = gk_b;
        nset = 2;
    }

    for (int i = tid; i < 2048; i += 128) {
        int c = i >> 5, p4 = (i & 31) * 4;
        *(float4*)(si + c * 128 + p4) = *(const float4*)(in + c * HW + n0 + p4);
    }
    for (int s = 0; s < nset; s++) {
        for (int i = tid; i < 512; i += 128) {
            int c = i >> 3, o = i & 7;
            swt[s * 512 + c * 8 + o] = ws[s][(og * 8 + o) * 64 + c];
        }
        if (tid < 8) sb2[s * 8 + tid] = bs[s][og * 8 + tid];
    }
    __syncthreads();

    u64 acc[3][4];
    #pragma unroll
    for (int s = 0; s < 3; s++)
        #pragma unroll
        for (int k = 0; k < 4; k++)
            acc[s][k] = pk2(sb2[s * 8 + 2 * k], sb2[s * 8 + 2 * k + 1]);

    if (side == 0) {
        for (int c = 0; c < 64; c++) {
            float iv = si[c * 128 + tid];
            u64 ivp = pk2(iv, iv);
            #pragma unroll
            for (int s = 0; s < 3; s++) {
                ulonglong2 wa = *(const ulonglong2*)(swt + s * 512 + c * 8);
                ulonglong2 wb = *(const ulonglong2*)(swt + s * 512 + c * 8 + 4);
                acc[s][0] = ffma2(ivp, wa.x, acc[s][0]);
                acc[s][1] = ffma2(ivp, wa.y, acc[s][1]);
                acc[s][2] = ffma2(ivp, wb.x, acc[s][2]);
                acc[s][3] = ffma2(ivp, wb.y, acc[s][3]);
            }
        }
    } else {
        for (int c = 0; c < 64; c++) {
            float iv = si[c * 128 + tid];
            u64 ivp = pk2(iv, iv);
            #pragma unroll
            for (int s = 0; s < 2; s++) {
                ulonglong2 wa = *(const ulonglong2*)(swt + s * 512 + c * 8);
                ulonglong2 wb = *(const ulonglong2*)(swt + s * 512 + c * 8 + 4);
                acc[s][0] = ffma2(ivp, wa.x, acc[s][0]);
                acc[s][1] = ffma2(ivp, wa.y, acc[s][1]);
                acc[s][2] = ffma2(ivp, wb.x, acc[s][2]);
                acc[s][3] = ffma2(ivp, wb.y, acc[s][3]);
            }
        }
    }

    // epilogue: q -> fp32; k -> bf16 hi/lo (per kind=side); v (side 0) -> bf16 hi/lo
    float* qdst = side ? g_gq : g_xq;
    __nv_bfloat16* KhD = g_bkh + (long)side * BATCH * CH * HW;
    __nv_bfloat16* KlD = g_bkl + (long)side * BATCH * CH * HW;
    #pragma unroll
    for (int k = 0; k < 4; k++) {
        int i0 = (b * CH + og * 8 + 2 * k) * HW + n0 + tid;
        float lo, hi;
        upk2(acc[0][k], lo, hi);
        qdst[i0] = lo; qdst[i0 + HW] = hi;
        upk2(acc[1][k], lo, hi);
        wrb(KhD, KlD, i0, lo); wrb(KhD, KlD, i0 + HW, hi);
        if (side == 0) {
            upk2(acc[2][k], lo, hi);
            wrb(g_bvh, g_bvl, i0, lo); wrb(g_bvh, g_bvl, i0 + HW, hi);
        }
    }
}

// ---------------- 4. flash attention: mma.sync + cp.async double buffer ----------------
// grid (64, B, 2), block 128 = 4 warps. CTA: 64 Q-rows; warp: 16 rows.
// dyn smem: 2 buffers x {Kh,Kl,Vh,Vl} each 64x72 bf16 (9216 B) = 73728 B.
__global__ void __launch_bounds__(128) kattn() {
    extern __shared__ __align__(16) uint8_t dyn[];

    const int tid = threadIdx.x;
    const int lane = tid & 31, wid = tid >> 5;
    const int tg = lane & 3, g = lane >> 2;
    const int b = blockIdx.y, kind = blockIdx.z;
    const int n0 = blockIdx.x * 64;
    const float* Qp = (kind ? g_gq : g_xq) + b * CH * HW;
    const __nv_bfloat16* Kh = g_bkh + ((long)kind * BATCH + b) * CH * HW;
    const __nv_bfloat16* Kl = g_bkl + ((long)kind * BATCH + b) * CH * HW;
    const __nv_bfloat16* Vh = g_bvh + (long)b * CH * HW;
    const __nv_bfloat16* Vl = g_bvl + (long)b * CH * HW;
    float* Op = (kind ? g_gout : g_xout) + b * CH * HW;

    const uint32_t sb = su32(dyn);

    // ---- stage Q (hi/lo) into buf0 area, load A-frags, then release buffer ----
    {
        __nv_bfloat16* Qh = (__nv_bfloat16*)dyn;           // [64][72]
        __nv_bfloat16* Ql = (__nv_bfloat16*)(dyn + 9216);
        for (int idx = tid; idx < 4096; idx += 128) {
            int i = idx & 63, c = idx >> 6;
            float a = Qp[c * HW + n0 + i];
            __nv_bfloat16 h = __float2bfloat16_rn(a);
            Qh[i * 72 + c] = h;
            Ql[i * 72 + c] = __float2bfloat16_rn(a - __bfloat162float(h));
        }
    }
    __syncthreads();

    uint32_t qh[4][4], ql[4][4];
    {
        int rl = lane & 15, ca = (lane >> 4) << 3;
        #pragma unroll
        for (int kc = 0; kc < 4; kc++) {
            uint32_t off = (uint32_t)(((16 * wid + rl) * 72 + 16 * kc + ca) * 2);
            ldsm4(qh[kc], sb + off);
            ldsm4(ql[kc], sb + 9216 + off);
        }
    }
    __syncthreads();

    float oacc[8][4];
    #pragma unroll
    for (int cb = 0; cb < 8; cb++) {
        oacc[cb][0] = 0.f; oacc[cb][1] = 0.f; oacc[cb][2] = 0.f; oacc[cb][3] = 0.f;
    }
    float mrow0 = -1e30f, mrow1 = -1e30f, lrow0 = 0.f, lrow1 = 0.f;

    const uint32_t k_off = (uint32_t)(((lane & 15) * 72 + ((lane >> 4) << 3)) * 2);
    const uint32_t v_off = (uint32_t)(((((lane >> 4) << 3) + (lane & 7)) * 72 +
                                      (((lane >> 3) & 1) << 3)) * 2);

    // prefetch tile 0 into buf0
    {
        #pragma unroll
        for (int u = 0; u < 4; u++) {
            int i = tid + u * 128;
            int row = i >> 3, ch = i & 7;
            uint32_t dst = sb + row * 144 + ch * 16;
            long go = (long)row * HW + ch * 8;
            cpa16(dst,          Kh + go);
            cpa16(dst + 9216,   Kl + go);
            cpa16(dst + 18432,  Vh + go);
            cpa16(dst + 27648,  Vl + go);
        }
        CPA_COMMIT();
    }

    for (int kt = 0; kt < 64; kt++) {
        const uint32_t bufc = sb + (uint32_t)(kt & 1) * 36864;

        if (kt < 63) {
            uint32_t bufn = sb + (uint32_t)((kt + 1) & 1) * 36864;
            int m0n = (kt + 1) * 64;
            #pragma unroll
            for (int u = 0; u < 4; u++) {
                int i = tid + u * 128;
                int row = i >> 3, ch = i & 7;
                uint32_t dst = bufn + row * 144 + ch * 16;
                long go = (long)row * HW + m0n + ch * 8;
                cpa16(dst,          Kh + go);
                cpa16(dst + 9216,   Kl + go);
                cpa16(dst + 18432,  Vh + go);
                cpa16(dst + 27648,  Vl + go);
            }
            CPA_COMMIT();
            CPA_WAIT1();
        } else {
            CPA_WAIT0();
        }
        __syncthreads();

        // ---- S = Q K^T (3 bf16 passes) ----
        float sa[8][4];
        #pragma unroll
        for (int nb = 0; nb < 8; nb++) {
            sa[nb][0] = 0.f; sa[nb][1] = 0.f; sa[nb][2] = 0.f; sa[nb][3] = 0.f;
        }
        #pragma unroll
        for (int kc = 0; kc < 4; kc++) {
            #pragma unroll
            for (int jb = 0; jb < 4; jb++) {
                uint32_t bh[4], bl[4];
                uint32_t toff = (uint32_t)((kc * 16 * 72 + jb * 16) * 2);
                ldsm4t(bh, bufc + k_off + toff);
                ldsm4t(bl, bufc + 9216 + k_off + toff);
                mma_bf16(sa[2 * jb],     qh[kc], bh[0], bh[1]);
                mma_bf16(sa[2 * jb],     qh[kc], bl[0], bl[1]);
                mma_bf16(sa[2 * jb],     ql[kc], bh[0], bh[1]);
                mma_bf16(sa[2 * jb + 1], qh[kc], bh[2], bh[3]);
                mma_bf16(sa[2 * jb + 1], qh[kc], bl[2], bl[3]);
                mma_bf16(sa[2 * jb + 1], ql[kc], bh[2], bh[3]);
            }
        }

        // ---- online softmax ----
        float tm0 = -1e30f, tm1 = -1e30f;
        #pragma unroll
        for (int nb = 0; nb < 8; nb++) {
            tm0 = fmaxf(tm0, fmaxf(sa[nb][0], sa[nb][1]));
            tm1 = fmaxf(tm1, fmaxf(sa[nb][2], sa[nb][3]));
        }
        tm0 = fmaxf(tm0, __shfl_xor_sync(0xffffffffu, tm0, 1));
        tm0 = fmaxf(tm0, __shfl_xor_sync(0xffffffffu, tm0, 2));
        tm1 = fmaxf(tm1, __shfl_xor_sync(0xffffffffu, tm1, 1));
        tm1 = fmaxf(tm1, __shfl_xor_sync(0xffffffffu, tm1, 2));
        float mn0 = fmaxf(mrow0, tm0), mn1 = fmaxf(mrow1, tm1);
        float corr0 = __expf(mrow0 - mn0), corr1 = __expf(mrow1 - mn1);
        mrow0 = mn0; mrow1 = mn1;

        float ps0 = 0.f, ps1 = 0.f;
        #pragma unroll
        for (int nb = 0; nb < 8; nb++) {
            sa[nb][0] = __expf(sa[nb][0] - mn0);
            sa[nb][1] = __expf(sa[nb][1] - mn0);
            sa[nb][2] = __expf(sa[nb][2] - mn1);
            sa[nb][3] = __expf(sa[nb][3] - mn1);
            ps0 += sa[nb][0] + sa[nb][1];
            ps1 += sa[nb][2] + sa[nb][3];
        }
        ps0 += __shfl_xor_sync(0xffffffffu, ps0, 1);
        ps0 += __shfl_xor_sync(0xffffffffu, ps0, 2);
        ps1 += __shfl_xor_sync(0xffffffffu, ps1, 1);
        ps1 += __shfl_xor_sync(0xffffffffu, ps1, 2);
        lrow0 = lrow0 * corr0 + ps0;
        lrow1 = lrow1 * corr1 + ps1;

        #pragma unroll
        for (int cb = 0; cb < 8; cb++) {
            oacc[cb][0] *= corr0; oacc[cb][1] *= corr0;
            oacc[cb][2] *= corr1; oacc[cb][3] *= corr1;
        }

        // ---- P a-frags in registers (hi/lo) ----
        uint32_t ph[4][4], pl[4][4];
        #pragma unroll
        for (int kc = 0; kc < 4; kc++) {
            split2(sa[2 * kc][0],     sa[2 * kc][1],     ph[kc][0], pl[kc][0]);
            split2(sa[2 * kc][2],     sa[2 * kc][3],     ph[kc][1], pl[kc][1]);
            split2(sa[2 * kc + 1][0], sa[2 * kc + 1][1], ph[kc][2], pl[kc][2]);
            split2(sa[2 * kc + 1][2], sa[2 * kc + 1][3], ph[kc][3], pl[kc][3]);
        }

        // ---- O += P V^T (3 bf16 passes) ----
        #pragma unroll
        for (int kc = 0; kc < 4; kc++) {
            #pragma unroll
            for (int cp = 0; cp < 4; cp++) {
                uint32_t bh[4], bl[4];
                uint32_t toff = (uint32_t)((cp * 16 * 72 + kc * 16) * 2);
                ldsm4(bh, bufc + 18432 + v_off + toff);
                ldsm4(bl, bufc + 27648 + v_off + toff);
                mma_bf16(oacc[2 * cp],     ph[kc], bh[0], bh[1]);
                mma_bf16(oacc[2 * cp],     ph[kc], bl[0], bl[1]);
                mma_bf16(oacc[2 * cp],     pl[kc], bh[0], bh[1]);
                mma_bf16(oacc[2 * cp + 1], ph[kc], bh[2], bh[3]);
                mma_bf16(oacc[2 * cp + 1], ph[kc], bl[2], bl[3]);
                mma_bf16(oacc[2 * cp + 1], pl[kc], bh[2], bh[3]);
            }
        }
        __syncthreads();
    }

    // ---- epilogue ----
    float inv0 = 1.f / lrow0, inv1 = 1.f / lrow1;
    int i0 = n0 + 16 * wid + g;
    #pragma unroll
    for (int cb = 0; cb < 8; cb++) {
        int c = 8 * cb + 2 * tg;
        Op[c * HW + i0]           = oacc[cb][0] * inv0;
        Op[(c + 1) * HW + i0]     = oacc[cb][1] * inv0;
        Op[c * HW + i0 + 8]       = oacc[cb][2] * inv1;
        Op[(c + 1) * HW + i0 + 8] = oacc[cb][3] * inv1;
    }
}

// ---------------- 5. combine ----------------
__global__ void kcombine(const float* __restrict__ gamma, const float* __restrict__ alpha) {
    int i = blockIdx.x * 256 + threadIdx.x;
    g_outb[i] = gamma[0] * g_xout[i] + alpha[0] * g_gout[i];
}

// ---------------- 6. plain conv3x3: 4 oc per block, optional fused final ----------------
__global__ void __launch_bounds__(256) kconv3(const float* __restrict__ w,
                                              const float* __restrict__ bias,
                                              int in_id, int out_id, int leaky_in,
                                              int finalize, float* __restrict__ dout) {
    const float* inb = pick_in(in_id);
    int b = blockIdx.z, ocg = blockIdx.y;

    __shared__ float ws[4 * 576];
    for (int i = threadIdx.x; i < 4 * 576; i += 256) {
        int o = i / 576, r = i % 576;
        ws[o * 576 + r] = w[(ocg * 4 + o) * 576 + r];
    }
    __syncthreads();

    int p = blockIdx.x * 1024 + threadIdx.x * 4;
    int row = p >> 6, col0 = p & 63;
    float acc[4][4];
    #pragma unroll
    for (int o = 0; o < 4; o++) {
        float bv = bias[ocg * 4 + o];
        #pragma unroll
        for (int u = 0; u < 4; u++) acc[o][u] = bv;
    }
    const float* in = inb + b * CH * HW;

    for (int ic = 0; ic < 64; ic++) {
        const float* ch = in + ic * HW;
        #pragma unroll
        for (int kh = 0; kh < 3; kh++) {
            int hh = row + kh - 1;
            if ((unsigned)hh >= 64u) continue;
            float v[6];
            #pragma unroll
            for (int u = 0; u < 6; u++) {
                int cc = col0 - 1 + u;
                float val = ((unsigned)cc < 64u) ? ch[hh * 64 + cc] : 0.f;
                if (leaky_in) val = val > 0.f ? val : 0.1f * val;
                v[u] = val;
            }
            #pragma unroll
            for (int o = 0; o < 4; o++) {
                const float* wr = &ws[o * 576 + ic * 9 + kh * 3];
                #pragma unroll
                for (int kw = 0; kw < 3; kw++) {
                    float wv = wr[kw];
                    acc[o][0] += wv * v[kw + 0];
                    acc[o][1] += wv * v[kw + 1];
                    acc[o][2] += wv * v[kw + 2];
                    acc[o][3] += wv * v[kw + 3];
                }
            }
        }
    }
    if (finalize) {
        #pragma unroll
        for (int o = 0; o < 4; o++) {
            int base = (b * CH + ocg * 4 + o) * HW + p;
            float4 scv = *(const float4*)(g_sc + base);
            float4 gov = *(const float4*)(g_gout + base);
            *(float4*)(dout + base) = make_float4(acc[o][0] + scv.x * gov.x,
                                                  acc[o][1] + scv.y * gov.y,
                                                  acc[o][2] + scv.z * gov.z,
                                                  acc[o][3] + scv.w * gov.w);
        }
    } else {
        float* outb = pick_out(out_id);
        #pragma unroll
        for (int o = 0; o < 4; o++) {
            float* op = outb + (b * CH + ocg * 4 + o) * HW + p;
            *(float4*)op = make_float4(acc[o][0], acc[o][1], acc[o][2], acc[o][3]);
        }
    }
}

// ---------------- 3b. 1x1 conv (shortcut path) ----------------
__global__ void k1x1(const float* __restrict__ w, const float* __restrict__ bias,
                     int in_id, int out_id) {
    const float* in = pick_in(in_id);
    float* out = pick_out(out_id);
    int b = blockIdx.z, og = blockIdx.y;
    int n0 = blockIdx.x * 128;

    __shared__ float si[64 * 128];
    __shared__ float sw[8 * 64];
    for (int i = threadIdx.x; i < 64 * 128; i += 128) {
        int c = i >> 7, px = i & 127;
        si[i] = in[(b * CH + c) * HW + n0 + px];
    }
    for (int i = threadIdx.x; i < 512; i += 128)
        sw[i] = w[(og * 8 + (i >> 6)) * 64 + (i & 63)];
    __syncthreads();

    float acc[8];
    #pragma unroll
    for (int o = 0; o < 8; o++) acc[o] = bias[og * 8 + o];
    for (int c = 0; c < 64; c++) {
        float iv = si[c * 128 + threadIdx.x];
        #pragma unroll
        for (int o = 0; o < 8; o++) acc[o] += sw[o * 64 + c] * iv;
    }
    #pragma unroll
    for (int o = 0; o < 8; o++)
        out[(b * CH + og * 8 + o) * HW + n0 + threadIdx.x] = acc[o];
}

extern "C" void kernel_launch(void* const* d_in, const int* in_sizes, int n_in,
                              void* d_out, int out_size) {
    const float* x       = (const float*)d_in[0];
    const float* guide   = (const float*)d_in[1];
    const float* lin_w   = (const float*)d_in[2];
    const float* lin_b   = (const float*)d_in[3];
    const float* coord_w = (const float*)d_in[4];
    const float* xq_w = (const float*)d_in[5];
    const float* xq_b = (const float*)d_in[6];
    const float* xk_w = (const float*)d_in[7];
    const float* xk_b = (const float*)d_in[8];
    const float* xv_w = (const float*)d_in[9];
    const float* xv_b = (const float*)d_in[10];
    const float* gq_w = (const float*)d_in[11];
    const float* gq_b = (const float*)d_in[12];
    const float* gk_w = (const float*)d_in[13];
    const float* gk_b = (const float*)d_in[14];
    const float* gamma = (const float*)d_in[15];
    const float* alpha = (const float*)d_in[16];
    const float* c1_w = (const float*)d_in[17];
    const float* c1_b = (const float*)d_in[18];
    const float* c2_w = (const float*)d_in[19];
    const float* c2_b = (const float*)d_in[20];
    const float* sc_w = (const float*)d_in[21];
    const float* sc_b = (const float*)d_in[22];
    float* out = (float*)d_out;

    cudaFuncSetAttribute(kattn, cudaFuncAttributeMaxDynamicSharedMemorySize, 73728);

    kstats<<<256, 256>>>(x, guide, lin_w, lin_b);
    kgated<<<dim3(4, 16, 4), 256>>>(x, guide, coord_w);

    kproj<<<dim3(32, 8, 4), 128>>>(xq_w, xq_b, xk_w, xk_b, xv_w, xv_b,
                                   gq_w, gq_b, gk_w, gk_b);

    kattn<<<dim3(64, BATCH, 2), 128, 73728>>>();

    kcombine<<<2048, 256>>>(gamma, alpha);

    kconv3<<<dim3(4, 16, BATCH), 256>>>(c1_w, c1_b, BUF_OUT, BUF_OT1, 1, 0, nullptr);
    k1x1<<<dim3(32, 8, BATCH), 128>>>(sc_w, sc_b, BUF_OUT, BUF_SC);
    kconv3<<<dim3(4, 16, BATCH), 256>>>(c2_w, c2_b, BUF_T1, 0, 1, 1, out);
}